// round 2
// baseline (speedup 1.0000x reference)
#include <cuda_runtime.h>

// Voronoi nearest-site via fine-grid candidate LUT, with distance comparisons
// reproducing the reference's fp32 arithmetic bit-for-bit:
//   a  = rn(rn(x0^2) + rn(x1^2))                  (jnp.sum(x*x))
//   e  = fmaf(x1, sy, rn(x0*sx))                  (cublas K=2 fma chain)
//   d2 = rn(rn(a - 2*e) + c_s), c_s = rn(rn(sx^2)+rn(sy^2))
//   argmin: ascending scan, strict <  (first-min tie-break)
//
// LUT: 96x96 cells, up to 4 candidate site ids per cell (packed u32, ascending,
// 0xFF pad). Band slack 1e-4 in distance guarantees excluded sites lose even
// under the reference formula's ~4e-7 d2 noise. Single-candidate cells need no
// distance math at all.

#define GR 96
#define NS 100
#define NCELL (GR * GR)

__device__ unsigned int g_grid[NCELL];
__device__ float2 g_pos[NS];
__device__ float4 g_rgbc[NS];   // x,y,z = rgb ; w = c_s (reference-rounded |s|^2)

__global__ void build_lut(const float* __restrict__ p) {
    int cell = blockIdx.x * blockDim.x + threadIdx.x;
    if (cell < NS) {
        float sx = p[1 + 5 * cell], sy = p[2 + 5 * cell];
        g_pos[cell] = make_float2(sx, sy);
        float cs = __fadd_rn(__fmul_rn(sx, sx), __fmul_rn(sy, sy));
        g_rgbc[cell] = make_float4(p[3 + 5 * cell], p[4 + 5 * cell], p[5 + 5 * cell], cs);
    }
    if (cell >= NCELL) return;

    int gy = cell / GR;
    int gx = cell - gy * GR;
    float cx = (gx + 0.5f) * (1.0f / GR);
    float cy = (gy + 0.5f) * (1.0f / GR);

    // Pass 1: exact nearest distance^2 from cell center.
    float best = 3.4e38f;
    for (int s = 0; s < NS; s++) {
        float dx = cx - p[1 + 5 * s];
        float dy = cy - p[2 + 5 * s];
        float d2 = fmaf(dx, dx, dy * dy);
        best = fminf(best, d2);
    }

    // Band: d(c,s) < d(c,s*) + 2r + slack.  2r = sqrt(2)/96; slack = 1e-4.
    float thr = sqrtf(best) + 0.01473139f + 1e-4f;
    float thr2 = thr * thr;

    // Pass 2: candidates in ascending site order.
    unsigned int entry = 0;
    int cnt = 0;
    for (int s = 0; s < NS; s++) {
        float dx = cx - p[1 + 5 * s];
        float dy = cy - p[2 + 5 * s];
        float d2 = fmaf(dx, dx, dy * dy);
        if (d2 <= thr2) {
            if (cnt < 4) entry |= ((unsigned int)s) << (8 * cnt);
            cnt++;
        }
    }
    if (cnt > 4) {
        // byte1 = 0xFE -> full-scan fallback
        entry = (entry & 0xFFu) | 0x0000FE00u | 0x00FF0000u | 0xFF000000u;
    } else {
        for (int k = cnt; k < 4; k++) entry |= 0xFFu << (8 * k);
    }
    g_grid[cell] = entry;
}

// Reference-exact d2
__device__ __forceinline__ float ref_d2(float a, float x0, float x1,
                                        float sx, float sy, float cs) {
    float e = __fmaf_rn(x1, sy, __fmul_rn(x0, sx));
    return __fadd_rn(__fsub_rn(a, __fmul_rn(2.0f, e)), cs);
}

__global__ void __launch_bounds__(256, 5) voronoi_main(
    const float2* __restrict__ x, float* __restrict__ out, int n)
{
    __shared__ unsigned int sgrid[NCELL];   // 36864 B
    __shared__ float2 spos[NS];
    __shared__ float4 srgbc[NS];

    for (int i = threadIdx.x; i < NCELL; i += blockDim.x) sgrid[i] = g_grid[i];
    if (threadIdx.x < NS) {
        spos[threadIdx.x] = g_pos[threadIdx.x];
        srgbc[threadIdx.x] = g_rgbc[threadIdx.x];
    }
    __syncthreads();

    int stride = gridDim.x * blockDim.x;
    for (int i = blockIdx.x * blockDim.x + threadIdx.x; i < n; i += stride) {
        float2 pt = x[i];
        int cx = (int)(pt.x * (float)GR);
        int cy = (int)(pt.y * (float)GR);
        cx = min(max(cx, 0), GR - 1);
        cy = min(max(cy, 0), GR - 1);

        unsigned int e = sgrid[cy * GR + cx];
        int idx = (int)(e & 0xFFu);

        if ((e >> 8) != 0x00FFFFFFu) {
            // reference-rounded |x|^2
            float a = __fadd_rn(__fmul_rn(pt.x, pt.x), __fmul_rn(pt.y, pt.y));
            float bd = 3.4e38f;
            int bi = 0;
            if (((e >> 8) & 0xFFu) == 0xFEu) {
                for (int s = 0; s < NS; s++) {
                    float2 sp = spos[s];
                    float d2 = ref_d2(a, pt.x, pt.y, sp.x, sp.y, srgbc[s].w);
                    if (d2 < bd) { bd = d2; bi = s; }
                }
            } else {
                #pragma unroll
                for (int k = 0; k < 4; k++) {
                    unsigned int c = (e >> (8 * k)) & 0xFFu;
                    if (c == 0xFFu) break;
                    float2 sp = spos[c];
                    float d2 = ref_d2(a, pt.x, pt.y, sp.x, sp.y, srgbc[c].w);
                    if (d2 < bd) { bd = d2; bi = (int)c; }
                }
            }
            idx = bi;
        }

        float4 c = srgbc[idx];
        out[3 * i + 0] = c.x;
        out[3 * i + 1] = c.y;
        out[3 * i + 2] = c.z;
    }
}

extern "C" void kernel_launch(void* const* d_in, const int* in_sizes, int n_in,
                              void* d_out, int out_size) {
    const float2* x = (const float2*)d_in[0];
    const float*  p = (const float*)d_in[1];
    float* out = (float*)d_out;
    int n = in_sizes[0] / 2;

    build_lut<<<(NCELL + 255) / 256, 256>>>(p);
    voronoi_main<<<760, 256>>>(x, out, n);
}